// round 2
// baseline (speedup 1.0000x reference)
#include <cuda_runtime.h>

#define HIDDEN 1024
#define NH     16
#define NKV    4
#define HD     64
#define BATCH  2
#define SEQ    2048
#define MROWS  (BATCH*SEQ)   // 4096
#define QDIM   (NH*HD)       // 1024
#define KVDIM  (NKV*HD)      // 256

// Scratch (allocation-free rule: __device__ globals)
__device__ float g_Q[MROWS * QDIM];
__device__ float g_K[MROWS * KVDIM];
__device__ float g_V[MROWS * KVDIM];
__device__ float g_A[MROWS * QDIM];

// ---------------------------------------------------------------------------
// SGEMM: C[M,N] = A[M,K] @ B[K,N] + bias[N]
// 128x128 block tile, k-step 16, 256 threads, 8x8 per-thread microtile.
// Requires M%128==0, N%128==0, K%16==0 (true for all four calls here).
// ---------------------------------------------------------------------------
__global__ __launch_bounds__(256) void sgemm_bias(
    const float* __restrict__ A, const float* __restrict__ B,
    const float* __restrict__ bias, float* __restrict__ C,
    int M, int N, int K)
{
    __shared__ float As[16][128];
    __shared__ float Bs[16][128];

    const int tid = threadIdx.x;
    const int bm = blockIdx.y * 128;
    const int bn = blockIdx.x * 128;
    const int tm = (tid >> 4) * 8;
    const int tn = (tid & 15) * 8;

    float acc[8][8];
#pragma unroll
    for (int i = 0; i < 8; i++)
#pragma unroll
        for (int j = 0; j < 8; j++) acc[i][j] = 0.f;

    for (int k0 = 0; k0 < K; k0 += 16) {
#pragma unroll
        for (int i = 0; i < 2; i++) {
            int id = tid * 2 + i;                  // 0..511
            int ar = id >> 2, ac = (id & 3) * 4;   // 128 rows x 4 float4 along k
            float4 av = *(const float4*)&A[(size_t)(bm + ar) * K + k0 + ac];
            As[ac + 0][ar] = av.x; As[ac + 1][ar] = av.y;
            As[ac + 2][ar] = av.z; As[ac + 3][ar] = av.w;
            int br = id >> 5, bc = (id & 31) * 4;  // 16 rows x 32 float4 along n
            *(float4*)&Bs[br][bc] = *(const float4*)&B[(size_t)(k0 + br) * N + bn + bc];
        }
        __syncthreads();
#pragma unroll
        for (int kk = 0; kk < 16; kk++) {
            float a[8], b[8];
            *(float4*)&a[0] = *(float4*)&As[kk][tm];
            *(float4*)&a[4] = *(float4*)&As[kk][tm + 4];
            *(float4*)&b[0] = *(float4*)&Bs[kk][tn];
            *(float4*)&b[4] = *(float4*)&Bs[kk][tn + 4];
#pragma unroll
            for (int i = 0; i < 8; i++)
#pragma unroll
                for (int j = 0; j < 8; j++)
                    acc[i][j] += a[i] * b[j];
        }
        __syncthreads();
    }

#pragma unroll
    for (int i = 0; i < 8; i++) {
        int row = bm + tm + i;
#pragma unroll
        for (int j = 0; j < 8; j += 4) {
            float4 o;
            o.x = acc[i][j + 0] + bias[bn + tn + j + 0];
            o.y = acc[i][j + 1] + bias[bn + tn + j + 1];
            o.z = acc[i][j + 2] + bias[bn + tn + j + 2];
            o.w = acc[i][j + 3] + bias[bn + tn + j + 3];
            *(float4*)&C[(size_t)row * N + bn + tn + j] = o;
        }
    }
}

// ---------------------------------------------------------------------------
// Flash-style GQA attention (NO 1/sqrt(d) scaling, no mask — matches ref).
// Grid: (SEQ/64, BATCH*NH). 256 threads. 64 q-rows per CTA, 64-key tiles.
// ---------------------------------------------------------------------------
#define SKQ 68  // padded row stride (floats) in smem tiles

__global__ __launch_bounds__(256) void flash_gqa(
    const float* __restrict__ Q, const float* __restrict__ K,
    const float* __restrict__ V, float* __restrict__ O)
{
    extern __shared__ float sm[];
    float* Qs = sm;                  // 64 x SKQ
    float* Ks = sm + 64 * SKQ;
    float* Vs = sm + 2 * 64 * SKQ;
    float* Ps = sm + 3 * 64 * SKQ;
    float* m_s  = sm + 4 * 64 * SKQ; // 64
    float* l_s  = m_s + 64;
    float* rs_s = l_s + 64;

    const int tid = threadIdx.x;
    const int qb = blockIdx.x;       // 0..31
    const int bh = blockIdx.y;       // 0..31
    const int b  = bh >> 4;
    const int h  = bh & 15;
    const int kh = h >> 2;           // 4 q-heads per kv-head

    const float* Qb = Q + (size_t)b * SEQ * QDIM  + h  * HD;
    const float* Kb = K + (size_t)b * SEQ * KVDIM + kh * HD;
    const float* Vb = V + (size_t)b * SEQ * KVDIM + kh * HD;

    // Load Q tile: 64 rows x 64 dims = 1024 float4
#pragma unroll
    for (int i = 0; i < 4; i++) {
        int id = tid + i * 256;      // 0..1023
        int r = id >> 4, c4 = id & 15;
        *(float4*)&Qs[r * SKQ + c4 * 4] =
            *(const float4*)&Qb[(size_t)(qb * 64 + r) * QDIM + c4 * 4];
    }
    if (tid < 64) { m_s[tid] = -1e30f; l_s[tid] = 0.f; }

    const int ty = tid >> 4, tx = tid & 15;
    const int r0 = ty * 4, c0 = tx * 4;

    float o[4][4];
#pragma unroll
    for (int i = 0; i < 4; i++)
#pragma unroll
        for (int j = 0; j < 4; j++) o[i][j] = 0.f;

    for (int kb = 0; kb < SEQ / 64; kb++) {
        __syncthreads();  // prior-iter consumers done before overwriting tiles
#pragma unroll
        for (int i = 0; i < 4; i++) {
            int id = tid + i * 256;
            int r = id >> 4, c4 = id & 15;
            *(float4*)&Ks[r * SKQ + c4 * 4] =
                *(const float4*)&Kb[(size_t)(kb * 64 + r) * KVDIM + c4 * 4];
            *(float4*)&Vs[r * SKQ + c4 * 4] =
                *(const float4*)&Vb[(size_t)(kb * 64 + r) * KVDIM + c4 * 4];
        }
        __syncthreads();

        // S = Q @ K^T  (4x4 per thread)
        float s[4][4];
#pragma unroll
        for (int i = 0; i < 4; i++)
#pragma unroll
            for (int j = 0; j < 4; j++) s[i][j] = 0.f;

#pragma unroll
        for (int d4 = 0; d4 < 16; d4++) {
            float4 q4[4], k4[4];
#pragma unroll
            for (int i = 0; i < 4; i++) q4[i] = *(float4*)&Qs[(r0 + i) * SKQ + d4 * 4];
#pragma unroll
            for (int j = 0; j < 4; j++) k4[j] = *(float4*)&Ks[(c0 + j) * SKQ + d4 * 4];
#pragma unroll
            for (int i = 0; i < 4; i++)
#pragma unroll
                for (int j = 0; j < 4; j++)
                    s[i][j] += q4[i].x * k4[j].x + q4[i].y * k4[j].y
                             + q4[i].z * k4[j].z + q4[i].w * k4[j].w;
        }

        // stage raw scores for row-stat reduction
#pragma unroll
        for (int i = 0; i < 4; i++)
#pragma unroll
            for (int j = 0; j < 4; j++)
                Ps[(r0 + i) * SKQ + c0 + j] = s[i][j];
        __syncthreads();

        if (tid < 64) {
            float mx = -1e30f;
#pragma unroll 8
            for (int c = 0; c < 64; c++) mx = fmaxf(mx, Ps[tid * SKQ + c]);
            float mo = m_s[tid];
            float mn = fmaxf(mo, mx);
            m_s[tid]  = mn;
            rs_s[tid] = __expf(mo - mn);
        }
        __syncthreads();

        // exponentiate + rescale running output
#pragma unroll
        for (int i = 0; i < 4; i++) {
            float mi  = m_s[r0 + i];
            float rsc = rs_s[r0 + i];
#pragma unroll
            for (int j = 0; j < 4; j++) {
                float p = __expf(s[i][j] - mi);
                s[i][j] = p;
                Ps[(r0 + i) * SKQ + c0 + j] = p;
                o[i][j] *= rsc;
            }
        }
        __syncthreads();

        if (tid < 64) {
            float sum = 0.f;
#pragma unroll 8
            for (int c = 0; c < 64; c++) sum += Ps[tid * SKQ + c];
            l_s[tid] = l_s[tid] * rs_s[tid] + sum;
        }

        // O += P @ V
#pragma unroll
        for (int k4 = 0; k4 < 16; k4++) {
            float4 pv[4], vv[4];
#pragma unroll
            for (int i = 0; i < 4; i++)  pv[i] = *(float4*)&Ps[(r0 + i) * SKQ + k4 * 4];
#pragma unroll
            for (int kk = 0; kk < 4; kk++) vv[kk] = *(float4*)&Vs[(k4 * 4 + kk) * SKQ + c0];
#pragma unroll
            for (int i = 0; i < 4; i++) {
                o[i][0] += pv[i].x * vv[0].x + pv[i].y * vv[1].x + pv[i].z * vv[2].x + pv[i].w * vv[3].x;
                o[i][1] += pv[i].x * vv[0].y + pv[i].y * vv[1].y + pv[i].z * vv[2].y + pv[i].w * vv[3].y;
                o[i][2] += pv[i].x * vv[0].z + pv[i].y * vv[1].z + pv[i].z * vv[2].z + pv[i].w * vv[3].z;
                o[i][3] += pv[i].x * vv[0].w + pv[i].y * vv[1].w + pv[i].z * vv[2].w + pv[i].w * vv[3].w;
            }
        }
    }
    __syncthreads();  // l_s final values visible to all

#pragma unroll
    for (int i = 0; i < 4; i++) {
        float inv = 1.f / l_s[r0 + i];
        int row = b * SEQ + qb * 64 + r0 + i;
        float4 w;
        w.x = o[i][0] * inv; w.y = o[i][1] * inv;
        w.z = o[i][2] * inv; w.w = o[i][3] * inv;
        *(float4*)&O[(size_t)row * QDIM + h * HD + c0] = w;
    }
}

// ---------------------------------------------------------------------------
extern "C" void kernel_launch(void* const* d_in, const int* in_sizes, int n_in,
                              void* d_out, int out_size)
{
    const float* x  = (const float*)d_in[0];
    const float* Wq = (const float*)d_in[1];
    const float* bq = (const float*)d_in[2];
    const float* Wk = (const float*)d_in[3];
    const float* bk = (const float*)d_in[4];
    const float* Wv = (const float*)d_in[5];
    const float* bv = (const float*)d_in[6];
    const float* Wo = (const float*)d_in[7];
    const float* bo = (const float*)d_in[8];
    float* out = (float*)d_out;

    float *Qp, *Kp, *Vp, *Ap;
    cudaGetSymbolAddress((void**)&Qp, g_Q);
    cudaGetSymbolAddress((void**)&Kp, g_K);
    cudaGetSymbolAddress((void**)&Vp, g_V);
    cudaGetSymbolAddress((void**)&Ap, g_A);

    // QKV projections
    sgemm_bias<<<dim3(QDIM / 128, MROWS / 128), 256>>>(x, Wq, bq, Qp, MROWS, QDIM, HIDDEN);
    sgemm_bias<<<dim3(KVDIM / 128, MROWS / 128), 256>>>(x, Wk, bk, Kp, MROWS, KVDIM, HIDDEN);
    sgemm_bias<<<dim3(KVDIM / 128, MROWS / 128), 256>>>(x, Wv, bv, Vp, MROWS, KVDIM, HIDDEN);

    // Flash attention
    size_t smem = (size_t)(4 * 64 * SKQ + 3 * 64) * sizeof(float);
    cudaFuncSetAttribute(flash_gqa, cudaFuncAttributeMaxDynamicSharedMemorySize, (int)smem);
    flash_gqa<<<dim3(SEQ / 64, BATCH * NH), 256, smem>>>(Qp, Kp, Vp, Ap);

    // Output projection -> d_out
    sgemm_bias<<<dim3(HIDDEN / 128, MROWS / 128), 256>>>(Ap, Wo, bo, out, MROWS, HIDDEN, HIDDEN);
}

// round 12
// speedup vs baseline: 1.8904x; 1.8904x over previous
#include <cuda_runtime.h>

#define HIDDEN 1024
#define NH     16
#define NKV    4
#define HD     64
#define BATCH  2
#define SEQ    2048
#define MROWS  (BATCH*SEQ)   // 4096
#define QDIM   (NH*HD)       // 1024
#define KVDIM  (NKV*HD)      // 256

// Scratch (allocation-free rule: __device__ globals)
__device__ float g_Q[MROWS * QDIM];
__device__ float g_K[MROWS * KVDIM];
__device__ float g_V[MROWS * KVDIM];
__device__ float g_A[MROWS * QDIM];

// Split fp32 into tf32 hi + tf32 lo (3xTF32 emulation)
__device__ __forceinline__ void split_tf32(float x, float& hi, float& lo) {
    hi = x;
    asm("cvt.rna.tf32.f32 %0, %0;" : "+f"(hi));
    lo = x - hi;
    asm("cvt.rna.tf32.f32 %0, %0;" : "+f"(lo));
}

// D += A(16x8,row) * B(8x8,col)  tf32, fp32 accum
__device__ __forceinline__ void mma8(float* d, const unsigned* a, const unsigned* b) {
    asm volatile(
        "mma.sync.aligned.m16n8k8.row.col.f32.tf32.tf32.f32 "
        "{%0,%1,%2,%3}, {%4,%5,%6,%7}, {%8,%9}, {%0,%1,%2,%3};\n"
        : "+f"(d[0]), "+f"(d[1]), "+f"(d[2]), "+f"(d[3])
        : "r"(a[0]), "r"(a[1]), "r"(a[2]), "r"(a[3]), "r"(b[0]), "r"(b[1]));
}

// 3xTF32: d += alo*bhi + ahi*blo + ahi*bhi
__device__ __forceinline__ void mma8_x3(float* d, const unsigned* ahi, const unsigned* alo,
                                        const unsigned* bhi, const unsigned* blo) {
    mma8(d, alo, bhi);
    mma8(d, ahi, blo);
    mma8(d, ahi, bhi);
}

// ---------------------------------------------------------------------------
// 3xTF32 GEMM: C[M,N] = A[M,K] @ B[K,N] + bias[N]  (near-fp32 accuracy)
// CTA tile 128x128, BK=32, 256 threads = 8 warps (4m x 2n), warp tile 32x64.
// Dynamic smem: As hi/lo 128x36 x2, Bs hi/lo 32x136 x2 = 71680 bytes.
// ---------------------------------------------------------------------------
#define AS_ST 36    // 36 mod 32 = 4  -> (4g+t) conflict-free
#define BS_ST 136   // 136 mod 32 = 8 -> (8t+g) conflict-free
#define GEMM_SMEM ((2*128*AS_ST + 2*32*BS_ST) * sizeof(float))

__global__ __launch_bounds__(256) void sgemm_tf32x3(
    const float* __restrict__ A, const float* __restrict__ B,
    const float* __restrict__ bias, float* __restrict__ C,
    int M, int N, int K)
{
    extern __shared__ float smg[];
    float* As_hi = smg;
    float* As_lo = As_hi + 128 * AS_ST;
    float* Bs_hi = As_lo + 128 * AS_ST;
    float* Bs_lo = Bs_hi + 32 * BS_ST;

    const int tid  = threadIdx.x;
    const int warp = tid >> 5, lane = tid & 31;
    const int g = lane >> 2, t = lane & 3;
    const int wm = warp >> 1, wn = warp & 1;
    const int bm = blockIdx.y * 128, bn = blockIdx.x * 128;

    float acc[2][8][4];
#pragma unroll
    for (int mt = 0; mt < 2; mt++)
#pragma unroll
        for (int nt = 0; nt < 8; nt++)
#pragma unroll
            for (int i = 0; i < 4; i++) acc[mt][nt][i] = 0.f;

    for (int k0 = 0; k0 < K; k0 += 32) {
        // Stage A tile: 128x32 floats = 1024 float4, 4 per thread
#pragma unroll
        for (int i = 0; i < 4; i++) {
            int idx = tid + i * 256;
            int r = idx >> 3, c4 = idx & 7;
            float4 v = *(const float4*)&A[(size_t)(bm + r) * K + k0 + c4 * 4];
            float* dh = &As_hi[r * AS_ST + c4 * 4];
            float* dl = &As_lo[r * AS_ST + c4 * 4];
            split_tf32(v.x, dh[0], dl[0]); split_tf32(v.y, dh[1], dl[1]);
            split_tf32(v.z, dh[2], dl[2]); split_tf32(v.w, dh[3], dl[3]);
        }
        // Stage B tile: 32x128 floats = 1024 float4
#pragma unroll
        for (int i = 0; i < 4; i++) {
            int idx = tid + i * 256;
            int r = idx >> 5, c4 = idx & 31;
            float4 v = *(const float4*)&B[(size_t)(k0 + r) * N + bn + c4 * 4];
            float* dh = &Bs_hi[r * BS_ST + c4 * 4];
            float* dl = &Bs_lo[r * BS_ST + c4 * 4];
            split_tf32(v.x, dh[0], dl[0]); split_tf32(v.y, dh[1], dl[1]);
            split_tf32(v.z, dh[2], dl[2]); split_tf32(v.w, dh[3], dl[3]);
        }
        __syncthreads();

#pragma unroll
        for (int ks = 0; ks < 4; ks++) {
            unsigned ah[2][4], al[2][4], bh[8][2], bl[8][2];
#pragma unroll
            for (int mt = 0; mt < 2; mt++) {
                int row = wm * 32 + mt * 16;
                int o00 = (row + g    ) * AS_ST + ks * 8 + t;
                int o10 = (row + g + 8) * AS_ST + ks * 8 + t;
                ah[mt][0] = __float_as_uint(As_hi[o00    ]);
                ah[mt][1] = __float_as_uint(As_hi[o10    ]);
                ah[mt][2] = __float_as_uint(As_hi[o00 + 4]);
                ah[mt][3] = __float_as_uint(As_hi[o10 + 4]);
                al[mt][0] = __float_as_uint(As_lo[o00    ]);
                al[mt][1] = __float_as_uint(As_lo[o10    ]);
                al[mt][2] = __float_as_uint(As_lo[o00 + 4]);
                al[mt][3] = __float_as_uint(As_lo[o10 + 4]);
            }
#pragma unroll
            for (int nt = 0; nt < 8; nt++) {
                int col = wn * 64 + nt * 8 + g;
                int o0 = (ks * 8 + t    ) * BS_ST + col;
                int o1 = (ks * 8 + t + 4) * BS_ST + col;
                bh[nt][0] = __float_as_uint(Bs_hi[o0]);
                bh[nt][1] = __float_as_uint(Bs_hi[o1]);
                bl[nt][0] = __float_as_uint(Bs_lo[o0]);
                bl[nt][1] = __float_as_uint(Bs_lo[o1]);
            }
#pragma unroll
            for (int mt = 0; mt < 2; mt++)
#pragma unroll
                for (int nt = 0; nt < 8; nt++)
                    mma8_x3(acc[mt][nt], ah[mt], al[mt], bh[nt], bl[nt]);
        }
        __syncthreads();
    }

    // Epilogue: c0/c1 at (row g, cols 2t,2t+1), c2/c3 at row g+8
#pragma unroll
    for (int mt = 0; mt < 2; mt++) {
        int row = bm + wm * 32 + mt * 16 + g;
#pragma unroll
        for (int nt = 0; nt < 8; nt++) {
            int col = bn + wn * 64 + nt * 8 + 2 * t;
            float bx = bias[col], by = bias[col + 1];
            float2 o0 = make_float2(acc[mt][nt][0] + bx, acc[mt][nt][1] + by);
            float2 o1 = make_float2(acc[mt][nt][2] + bx, acc[mt][nt][3] + by);
            *(float2*)&C[(size_t)row * N + col]       = o0;
            *(float2*)&C[(size_t)(row + 8) * N + col] = o1;
        }
    }
}

// ---------------------------------------------------------------------------
// Flash GQA attention, 3xTF32 tensor cores (NO 1/sqrt(d) scaling, no mask).
// Grid: (SEQ/64, BATCH*NH). 128 threads = 4 warps; warp w owns q-rows
// [w*16, w*16+16). 64-key tiles, online softmax in fragment registers.
// Dynamic smem: Ks hi/lo 64x68 x2 | Vs hi/lo 64x72 x2 | Ps f32 4x16x68
//             = (8704 + 9216 + 4352) floats = 89088 bytes.
// ---------------------------------------------------------------------------
#define KS_ST 68    // 68 mod 32 = 4  -> (4g+t) conflict-free (K^T B-frags)
#define VS_ST 72    // 72 mod 32 = 8  -> (8t+g) conflict-free (V B-frags)
#define PS_ST 68    // 68 mod 32 = 4  -> (4g+t) conflict-free (P A-frags)
#define FLASH_SMEM ((2*64*KS_ST + 2*64*VS_ST + 4*16*PS_ST) * sizeof(float))

__global__ __launch_bounds__(128) void flash_gqa_tc(
    const float* __restrict__ Q, const float* __restrict__ K,
    const float* __restrict__ V, float* __restrict__ O)
{
    extern __shared__ float sm[];
    float* Ks_hi = sm;                        // 64*KS_ST
    float* Ks_lo = Ks_hi + 64 * KS_ST;
    float* Vs_hi = Ks_lo + 64 * KS_ST;        // 64*VS_ST
    float* Vs_lo = Vs_hi + 64 * VS_ST;
    float* Ps    = Vs_lo + 64 * VS_ST;        // 4 warps x 16*PS_ST (f32)

    const int tid = threadIdx.x;
    const int w = tid >> 5, lane = tid & 31;
    const int g = lane >> 2, t = lane & 3;
    const int qb = blockIdx.x;
    const int bh = blockIdx.y;
    const int b = bh >> 4, h = bh & 15, kh = h >> 2;

    const float* Qb = Q + (size_t)b * SEQ * QDIM  + h  * HD;
    const float* Kb = K + (size_t)b * SEQ * KVDIM + kh * HD;
    const float* Vb = V + (size_t)b * SEQ * KVDIM + kh * HD;

    // Stage Q tile (64x64, f32) through Ks_hi, then split into persistent regs
#pragma unroll
    for (int i = 0; i < 8; i++) {
        int idx = tid + i * 128;           // 0..1023
        int r = idx >> 4, c4 = idx & 15;
        *(float4*)&Ks_hi[r * KS_ST + c4 * 4] =
            *(const float4*)&Qb[(size_t)(qb * 64 + r) * QDIM + c4 * 4];
    }
    __syncthreads();

    unsigned qh[8][4], ql[8][4];
    {
        int row = w * 16;
#pragma unroll
        for (int ks = 0; ks < 8; ks++) {
            float hi, lo;
            split_tf32(Ks_hi[(row + g    ) * KS_ST + ks * 8 + t    ], hi, lo);
            qh[ks][0] = __float_as_uint(hi); ql[ks][0] = __float_as_uint(lo);
            split_tf32(Ks_hi[(row + g + 8) * KS_ST + ks * 8 + t    ], hi, lo);
            qh[ks][1] = __float_as_uint(hi); ql[ks][1] = __float_as_uint(lo);
            split_tf32(Ks_hi[(row + g    ) * KS_ST + ks * 8 + t + 4], hi, lo);
            qh[ks][2] = __float_as_uint(hi); ql[ks][2] = __float_as_uint(lo);
            split_tf32(Ks_hi[(row + g + 8) * KS_ST + ks * 8 + t + 4], hi, lo);
            qh[ks][3] = __float_as_uint(hi); ql[ks][3] = __float_as_uint(lo);
        }
    }

    float o[8][4];
#pragma unroll
    for (int nt = 0; nt < 8; nt++)
#pragma unroll
        for (int i = 0; i < 4; i++) o[nt][i] = 0.f;
    float m0 = -1e30f, m1 = -1e30f, l0 = 0.f, l1 = 0.f;

    for (int kb = 0; kb < SEQ / 64; kb++) {
        __syncthreads();   // all consumers of previous K/V tile done
#pragma unroll
        for (int i = 0; i < 8; i++) {
            int idx = tid + i * 128;
            int r = idx >> 4, c4 = idx & 15;
            float4 kv = *(const float4*)&Kb[(size_t)(kb * 64 + r) * KVDIM + c4 * 4];
            float* kh_ = &Ks_hi[r * KS_ST + c4 * 4];
            float* kl_ = &Ks_lo[r * KS_ST + c4 * 4];
            split_tf32(kv.x, kh_[0], kl_[0]); split_tf32(kv.y, kh_[1], kl_[1]);
            split_tf32(kv.z, kh_[2], kl_[2]); split_tf32(kv.w, kh_[3], kl_[3]);
            float4 vv = *(const float4*)&Vb[(size_t)(kb * 64 + r) * KVDIM + c4 * 4];
            float* vh_ = &Vs_hi[r * VS_ST + c4 * 4];
            float* vl_ = &Vs_lo[r * VS_ST + c4 * 4];
            split_tf32(vv.x, vh_[0], vl_[0]); split_tf32(vv.y, vh_[1], vl_[1]);
            split_tf32(vv.z, vh_[2], vl_[2]); split_tf32(vv.w, vh_[3], vl_[3]);
        }
        __syncthreads();

        // S = Q @ K^T : 8 n-tiles of 16x8, 3xTF32
        float s[8][4];
#pragma unroll
        for (int nt = 0; nt < 8; nt++)
#pragma unroll
            for (int i = 0; i < 4; i++) s[nt][i] = 0.f;

#pragma unroll
        for (int ks = 0; ks < 8; ks++) {
#pragma unroll
            for (int nt = 0; nt < 8; nt++) {
                int o0 = (nt * 8 + g) * KS_ST + ks * 8 + t;
                unsigned bfh[2], bfl[2];
                bfh[0] = __float_as_uint(Ks_hi[o0    ]);
                bfh[1] = __float_as_uint(Ks_hi[o0 + 4]);
                bfl[0] = __float_as_uint(Ks_lo[o0    ]);
                bfl[1] = __float_as_uint(Ks_lo[o0 + 4]);
                mma8_x3(s[nt], qh[ks], ql[ks], bfh, bfl);
            }
        }

        // Online softmax: rows g (regs 0,1) and g+8 (regs 2,3)
        float mx0 = -1e30f, mx1 = -1e30f;
#pragma unroll
        for (int nt = 0; nt < 8; nt++) {
            mx0 = fmaxf(mx0, fmaxf(s[nt][0], s[nt][1]));
            mx1 = fmaxf(mx1, fmaxf(s[nt][2], s[nt][3]));
        }
        mx0 = fmaxf(mx0, __shfl_xor_sync(0xffffffffu, mx0, 1));
        mx0 = fmaxf(mx0, __shfl_xor_sync(0xffffffffu, mx0, 2));
        mx1 = fmaxf(mx1, __shfl_xor_sync(0xffffffffu, mx1, 1));
        mx1 = fmaxf(mx1, __shfl_xor_sync(0xffffffffu, mx1, 2));

        float mn0 = fmaxf(m0, mx0), mn1 = fmaxf(m1, mx1);
        float sc0 = __expf(m0 - mn0), sc1 = __expf(m1 - mn1);
        m0 = mn0; m1 = mn1;

        float rs0 = 0.f, rs1 = 0.f;
        float* pw = &Ps[w * 16 * PS_ST];
#pragma unroll
        for (int nt = 0; nt < 8; nt++) {
            float p0 = __expf(s[nt][0] - mn0);
            float p1 = __expf(s[nt][1] - mn0);
            float p2 = __expf(s[nt][2] - mn1);
            float p3 = __expf(s[nt][3] - mn1);
            rs0 += p0 + p1; rs1 += p2 + p3;
            int col = nt * 8 + 2 * t;
            *(float2*)&pw[ g      * PS_ST + col] = make_float2(p0, p1);
            *(float2*)&pw[(g + 8) * PS_ST + col] = make_float2(p2, p3);
            o[nt][0] *= sc0; o[nt][1] *= sc0;
            o[nt][2] *= sc1; o[nt][3] *= sc1;
        }
        rs0 += __shfl_xor_sync(0xffffffffu, rs0, 1);
        rs0 += __shfl_xor_sync(0xffffffffu, rs0, 2);
        rs1 += __shfl_xor_sync(0xffffffffu, rs1, 1);
        rs1 += __shfl_xor_sync(0xffffffffu, rs1, 2);
        l0 = l0 * sc0 + rs0;
        l1 = l1 * sc1 + rs1;
        __syncwarp();

        // O += P @ V (3xTF32; P split on the fly from f32 smem)
#pragma unroll
        for (int ks = 0; ks < 8; ks++) {
            unsigned pah[4], pal[4];
            float hi, lo;
            split_tf32(pw[ g      * PS_ST + ks * 8 + t    ], hi, lo);
            pah[0] = __float_as_uint(hi); pal[0] = __float_as_uint(lo);
            split_tf32(pw[(g + 8) * PS_ST + ks * 8 + t    ], hi, lo);
            pah[1] = __float_as_uint(hi); pal[1] = __float_as_uint(lo);
            split_tf32(pw[ g      * PS_ST + ks * 8 + t + 4], hi, lo);
            pah[2] = __float_as_uint(hi); pal[2] = __float_as_uint(lo);
            split_tf32(pw[(g + 8) * PS_ST + ks * 8 + t + 4], hi, lo);
            pah[3] = __float_as_uint(hi); pal[3] = __float_as_uint(lo);
#pragma unroll
            for (int nt = 0; nt < 8; nt++) {
                int o0 = (ks * 8 + t    ) * VS_ST + nt * 8 + g;
                int o1 = (ks * 8 + t + 4) * VS_ST + nt * 8 + g;
                unsigned vbh[2], vbl[2];
                vbh[0] = __float_as_uint(Vs_hi[o0]);
                vbh[1] = __float_as_uint(Vs_hi[o1]);
                vbl[0] = __float_as_uint(Vs_lo[o0]);
                vbl[1] = __float_as_uint(Vs_lo[o1]);
                mma8_x3(o[nt], pah, pal, vbh, vbl);
            }
        }
    }

    // Epilogue
    float inv0 = 1.f / l0, inv1 = 1.f / l1;
    int row0 = b * SEQ + qb * 64 + w * 16 + g;
#pragma unroll
    for (int nt = 0; nt < 8; nt++) {
        int col = h * HD + nt * 8 + 2 * t;
        *(float2*)&O[(size_t)row0 * QDIM + col] =
            make_float2(o[nt][0] * inv0, o[nt][1] * inv0);
        *(float2*)&O[(size_t)(row0 + 8) * QDIM + col] =
            make_float2(o[nt][2] * inv1, o[nt][3] * inv1);
    }
}

// ---------------------------------------------------------------------------
extern "C" void kernel_launch(void* const* d_in, const int* in_sizes, int n_in,
                              void* d_out, int out_size)
{
    const float* x  = (const float*)d_in[0];
    const float* Wq = (const float*)d_in[1];
    const float* bq = (const float*)d_in[2];
    const float* Wk = (const float*)d_in[3];
    const float* bk = (const float*)d_in[4];
    const float* Wv = (const float*)d_in[5];
    const float* bv = (const float*)d_in[6];
    const float* Wo = (const float*)d_in[7];
    const float* bo = (const float*)d_in[8];
    float* out = (float*)d_out;

    float *Qp, *Kp, *Vp, *Ap;
    cudaGetSymbolAddress((void**)&Qp, g_Q);
    cudaGetSymbolAddress((void**)&Kp, g_K);
    cudaGetSymbolAddress((void**)&Vp, g_V);
    cudaGetSymbolAddress((void**)&Ap, g_A);

    cudaFuncSetAttribute(sgemm_tf32x3,
                         cudaFuncAttributeMaxDynamicSharedMemorySize, (int)GEMM_SMEM);
    cudaFuncSetAttribute(flash_gqa_tc,
                         cudaFuncAttributeMaxDynamicSharedMemorySize, (int)FLASH_SMEM);

    // QKV projections (3xTF32 tensor cores)
    sgemm_tf32x3<<<dim3(QDIM  / 128, MROWS / 128), 256, GEMM_SMEM>>>(x, Wq, bq, Qp, MROWS, QDIM,  HIDDEN);
    sgemm_tf32x3<<<dim3(KVDIM / 128, MROWS / 128), 256, GEMM_SMEM>>>(x, Wk, bk, Kp, MROWS, KVDIM, HIDDEN);
    sgemm_tf32x3<<<dim3(KVDIM / 128, MROWS / 128), 256, GEMM_SMEM>>>(x, Wv, bv, Vp, MROWS, KVDIM, HIDDEN);

    // Flash attention (3xTF32 tensor cores)
    flash_gqa_tc<<<dim3(SEQ / 64, BATCH * NH), 128, FLASH_SMEM>>>(Qp, Kp, Vp, Ap);

    // Output projection -> d_out
    sgemm_tf32x3<<<dim3(HIDDEN / 128, MROWS / 128), 256, GEMM_SMEM>>>(Ap, Wo, bo, out, MROWS, HIDDEN, HIDDEN);
}

// round 13
// speedup vs baseline: 3.1677x; 1.6756x over previous
#include <cuda_runtime.h>
#include <cuda_bf16.h>

#define HIDDEN 1024
#define NH     16
#define NKV    4
#define HD     64
#define BATCH  2
#define SEQ    2048
#define MROWS  (BATCH*SEQ)   // 4096
#define QDIM   (NH*HD)       // 1024
#define KVDIM  (NKV*HD)      // 256

// Scratch (allocation-free rule: __device__ globals)
__device__ float g_Q[MROWS * QDIM];
__device__ float g_K[MROWS * KVDIM];
__device__ float g_V[MROWS * KVDIM];
__device__ float g_A[MROWS * QDIM];

// Pack two floats into one bf162 register (x0 -> low half)
__device__ __forceinline__ unsigned pack2(float x0, float x1) {
    __nv_bfloat162 v = __floats2bfloat162_rn(x0, x1);
    return *(unsigned*)&v;
}

// Split two floats into bf16 hi-pair + bf16 lo-pair (3xBF16 emulation)
__device__ __forceinline__ void split2(float x0, float x1, unsigned& hi, unsigned& lo) {
    float h0 = __bfloat162float(__float2bfloat16(x0));
    float h1 = __bfloat162float(__float2bfloat16(x1));
    hi = pack2(h0, h1);
    lo = pack2(x0 - h0, x1 - h1);
}

// D += A(16x16,row) * B(16x8,col)  bf16, fp32 accum
__device__ __forceinline__ void mma16(float* d, const unsigned* a, const unsigned* b) {
    asm volatile(
        "mma.sync.aligned.m16n8k16.row.col.f32.bf16.bf16.f32 "
        "{%0,%1,%2,%3}, {%4,%5,%6,%7}, {%8,%9}, {%0,%1,%2,%3};\n"
        : "+f"(d[0]), "+f"(d[1]), "+f"(d[2]), "+f"(d[3])
        : "r"(a[0]), "r"(a[1]), "r"(a[2]), "r"(a[3]), "r"(b[0]), "r"(b[1]));
}

// 3xBF16: d += alo*bhi + ahi*blo + ahi*bhi
__device__ __forceinline__ void mma16_x3(float* d, const unsigned* ahi, const unsigned* alo,
                                         const unsigned* bhi, const unsigned* blo) {
    mma16(d, alo, bhi);
    mma16(d, ahi, blo);
    mma16(d, ahi, bhi);
}

// ---------------------------------------------------------------------------
// 3xBF16 GEMM: C[M,N] = A[M,K] @ B[K,N] + bias[N]  (near-fp32 accuracy)
// CTA tile 128x128, BK=32 (2 k-chunks of 16), 256 thr = 8 warps (4m x 2n),
// warp tile 32x64. Smem: bf162 words, row stride 20 -> conflict-free frags.
// ---------------------------------------------------------------------------
#define GA_ST 20   // (20g+t) mod 32 distinct over the 32 lanes

__global__ __launch_bounds__(256, 2) void sgemm_bf16x3(
    const float* __restrict__ A, const float* __restrict__ B,
    const float* __restrict__ bias, float* __restrict__ C,
    int M, int N, int K)
{
    __shared__ unsigned As_hi[128 * GA_ST], As_lo[128 * GA_ST];  // [m][kpair]
    __shared__ unsigned Bs_hi[128 * GA_ST], Bs_lo[128 * GA_ST];  // [n][kpair] (transposed)

    const int tid  = threadIdx.x;
    const int warp = tid >> 5, lane = tid & 31;
    const int g = lane >> 2, t = lane & 3;
    const int wm = warp >> 1, wn = warp & 1;
    const int bm = blockIdx.y * 128, bn = blockIdx.x * 128;

    float acc[2][8][4];
#pragma unroll
    for (int mt = 0; mt < 2; mt++)
#pragma unroll
        for (int nt = 0; nt < 8; nt++)
#pragma unroll
            for (int i = 0; i < 4; i++) acc[mt][nt][i] = 0.f;

    for (int k0 = 0; k0 < K; k0 += 32) {
        // Stage A tile 128x32: pairs along k
#pragma unroll
        for (int i = 0; i < 4; i++) {
            int id = tid + i * 256;
            int r = id >> 3, c4 = id & 7;
            float4 v = *(const float4*)&A[(size_t)(bm + r) * K + k0 + c4 * 4];
            unsigned h0, l0, h1, l1;
            split2(v.x, v.y, h0, l0);
            split2(v.z, v.w, h1, l1);
            *(uint2*)&As_hi[r * GA_ST + 2 * c4] = make_uint2(h0, h1);
            *(uint2*)&As_lo[r * GA_ST + 2 * c4] = make_uint2(l0, l1);
        }
        // Stage B tile 32x128 transposed: word (n, kp) = {B[k0+2kp][n], B[k0+2kp+1][n]}
#pragma unroll
        for (int i = 0; i < 8; i++) {
            int id = tid + i * 256;
            int n = id & 127, kp = id >> 7;
            float b0 = B[(size_t)(k0 + 2 * kp    ) * N + bn + n];
            float b1 = B[(size_t)(k0 + 2 * kp + 1) * N + bn + n];
            unsigned h, l;
            split2(b0, b1, h, l);
            Bs_hi[n * GA_ST + kp] = h;
            Bs_lo[n * GA_ST + kp] = l;
        }
        __syncthreads();

#pragma unroll
        for (int kc = 0; kc < 2; kc++) {
            unsigned ah[2][4], al[2][4];
#pragma unroll
            for (int mt = 0; mt < 2; mt++) {
                int r0 = (wm * 32 + mt * 16 + g    ) * GA_ST + 8 * kc;
                int r1 = (wm * 32 + mt * 16 + g + 8) * GA_ST + 8 * kc;
                ah[mt][0] = As_hi[r0 + t];     al[mt][0] = As_lo[r0 + t];
                ah[mt][1] = As_hi[r1 + t];     al[mt][1] = As_lo[r1 + t];
                ah[mt][2] = As_hi[r0 + 4 + t]; al[mt][2] = As_lo[r0 + 4 + t];
                ah[mt][3] = As_hi[r1 + 4 + t]; al[mt][3] = As_lo[r1 + 4 + t];
            }
#pragma unroll
            for (int nt = 0; nt < 8; nt++) {
                int nb = (wn * 64 + nt * 8 + g) * GA_ST + 8 * kc;
                unsigned bh[2], bl[2];
                bh[0] = Bs_hi[nb + t];     bl[0] = Bs_lo[nb + t];
                bh[1] = Bs_hi[nb + 4 + t]; bl[1] = Bs_lo[nb + 4 + t];
#pragma unroll
                for (int mt = 0; mt < 2; mt++)
                    mma16_x3(acc[mt][nt], ah[mt], al[mt], bh, bl);
            }
        }
        __syncthreads();
    }

    // Epilogue: c0/c1 at (row g, cols 2t,2t+1), c2/c3 at row g+8
#pragma unroll
    for (int mt = 0; mt < 2; mt++) {
        int row = bm + wm * 32 + mt * 16 + g;
#pragma unroll
        for (int nt = 0; nt < 8; nt++) {
            int col = bn + wn * 64 + nt * 8 + 2 * t;
            float bx = bias[col], by = bias[col + 1];
            float2 o0 = make_float2(acc[mt][nt][0] + bx, acc[mt][nt][1] + by);
            float2 o1 = make_float2(acc[mt][nt][2] + bx, acc[mt][nt][3] + by);
            *(float2*)&C[(size_t)row * N + col]       = o0;
            *(float2*)&C[(size_t)(row + 8) * N + col] = o1;
        }
    }
}

// ---------------------------------------------------------------------------
// Flash GQA attention, 3xBF16 tensor cores (NO 1/sqrt(d) scaling, no mask).
// Grid: (SEQ/64, BATCH*NH). 128 threads = 4 warps; warp w owns q-rows
// [w*16, w*16+16). 64-key tiles, online softmax; P stays in registers
// (S C-frag == PV A-frag for m16n8k16).
// Dynamic smem: Qs,Ks,Vt x (hi,lo), each 64 x 36 words = 55296 bytes.
// ---------------------------------------------------------------------------
#define FL_ST 36   // (4g+t) mod 32 distinct -> conflict-free fragment loads
#define FLASH_SMEM (6 * 64 * FL_ST * sizeof(unsigned))

__global__ __launch_bounds__(128, 4) void flash_gqa_bf16(
    const float* __restrict__ Q, const float* __restrict__ K,
    const float* __restrict__ V, float* __restrict__ O)
{
    extern __shared__ unsigned smu[];
    unsigned* Qs_hi = smu;                      // [qrow][dpair]
    unsigned* Qs_lo = Qs_hi + 64 * FL_ST;
    unsigned* Ks_hi = Qs_lo + 64 * FL_ST;       // [key][dpair]
    unsigned* Ks_lo = Ks_hi + 64 * FL_ST;
    unsigned* Vt_hi = Ks_lo + 64 * FL_ST;       // [d][keypair] (transposed)
    unsigned* Vt_lo = Vt_hi + 64 * FL_ST;

    const int tid = threadIdx.x;
    const int w = tid >> 5, lane = tid & 31;
    const int g = lane >> 2, t = lane & 3;
    const int qb = blockIdx.x;
    const int bh = blockIdx.y;
    const int b = bh >> 4, h = bh & 15, kh = h >> 2;

    const float* Qb = Q + (size_t)b * SEQ * QDIM  + h  * HD;
    const float* Kb = K + (size_t)b * SEQ * KVDIM + kh * HD;
    const float* Vb = V + (size_t)b * SEQ * KVDIM + kh * HD;

    // Stage Q tile (64x64) as bf16 hi/lo pairs along d
#pragma unroll
    for (int i = 0; i < 8; i++) {
        int id = tid + i * 128;
        int r = id >> 4, c4 = id & 15;
        float4 v = *(const float4*)&Qb[(size_t)(qb * 64 + r) * QDIM + c4 * 4];
        unsigned h0, l0, h1, l1;
        split2(v.x, v.y, h0, l0);
        split2(v.z, v.w, h1, l1);
        *(uint2*)&Qs_hi[r * FL_ST + 2 * c4] = make_uint2(h0, h1);
        *(uint2*)&Qs_lo[r * FL_ST + 2 * c4] = make_uint2(l0, l1);
    }

    float o[8][4];
#pragma unroll
    for (int nt = 0; nt < 8; nt++)
#pragma unroll
        for (int i = 0; i < 4; i++) o[nt][i] = 0.f;
    float m0 = -1e30f, m1 = -1e30f, l0s = 0.f, l1s = 0.f;

    for (int kb = 0; kb < SEQ / 64; kb++) {
        __syncthreads();   // prev-tile consumers done (also orders Q staging on kb=0)
        // Stage K tile (pairs along d)
#pragma unroll
        for (int i = 0; i < 8; i++) {
            int id = tid + i * 128;
            int r = id >> 4, c4 = id & 15;
            float4 kv = *(const float4*)&Kb[(size_t)(kb * 64 + r) * KVDIM + c4 * 4];
            unsigned h0, l0, h1, l1;
            split2(kv.x, kv.y, h0, l0);
            split2(kv.z, kv.w, h1, l1);
            *(uint2*)&Ks_hi[r * FL_ST + 2 * c4] = make_uint2(h0, h1);
            *(uint2*)&Ks_lo[r * FL_ST + 2 * c4] = make_uint2(l0, l1);
        }
        // Stage V transposed: word (d, kp) = {V[2kp][d], V[2kp+1][d]}
#pragma unroll
        for (int i = 0; i < 16; i++) {
            int id = tid + i * 128;
            int kp = id >> 6, d = id & 63;
            float v0 = Vb[(size_t)(kb * 64 + 2 * kp    ) * KVDIM + d];
            float v1 = Vb[(size_t)(kb * 64 + 2 * kp + 1) * KVDIM + d];
            unsigned hh, ll;
            split2(v0, v1, hh, ll);
            Vt_hi[d * FL_ST + kp] = hh;
            Vt_lo[d * FL_ST + kp] = ll;
        }
        __syncthreads();

        // S = Q @ K^T : 8 n-tiles of 16x8, K-dim in 4 chunks of 16
        float s[8][4];
#pragma unroll
        for (int nt = 0; nt < 8; nt++)
#pragma unroll
            for (int i = 0; i < 4; i++) s[nt][i] = 0.f;

        const int rq0 = (w * 16 + g    ) * FL_ST;
        const int rq1 = (w * 16 + g + 8) * FL_ST;
#pragma unroll
        for (int kc = 0; kc < 4; kc++) {
            unsigned qh[4], ql[4];
            qh[0] = Qs_hi[rq0 + 8 * kc + t];     ql[0] = Qs_lo[rq0 + 8 * kc + t];
            qh[1] = Qs_hi[rq1 + 8 * kc + t];     ql[1] = Qs_lo[rq1 + 8 * kc + t];
            qh[2] = Qs_hi[rq0 + 8 * kc + 4 + t]; ql[2] = Qs_lo[rq0 + 8 * kc + 4 + t];
            qh[3] = Qs_hi[rq1 + 8 * kc + 4 + t]; ql[3] = Qs_lo[rq1 + 8 * kc + 4 + t];
#pragma unroll
            for (int nt = 0; nt < 8; nt++) {
                int rn = (nt * 8 + g) * FL_ST + 8 * kc;
                unsigned bh_[2], bl_[2];
                bh_[0] = Ks_hi[rn + t];     bl_[0] = Ks_lo[rn + t];
                bh_[1] = Ks_hi[rn + 4 + t]; bl_[1] = Ks_lo[rn + 4 + t];
                mma16_x3(s[nt], qh, ql, bh_, bl_);
            }
        }

        // Online softmax: rows g (regs 0,1) and g+8 (regs 2,3)
        float mx0 = -1e30f, mx1 = -1e30f;
#pragma unroll
        for (int nt = 0; nt < 8; nt++) {
            mx0 = fmaxf(mx0, fmaxf(s[nt][0], s[nt][1]));
            mx1 = fmaxf(mx1, fmaxf(s[nt][2], s[nt][3]));
        }
        mx0 = fmaxf(mx0, __shfl_xor_sync(0xffffffffu, mx0, 1));
        mx0 = fmaxf(mx0, __shfl_xor_sync(0xffffffffu, mx0, 2));
        mx1 = fmaxf(mx1, __shfl_xor_sync(0xffffffffu, mx1, 1));
        mx1 = fmaxf(mx1, __shfl_xor_sync(0xffffffffu, mx1, 2));

        float mn0 = fmaxf(m0, mx0), mn1 = fmaxf(m1, mx1);
        float sc0 = __expf(m0 - mn0), sc1 = __expf(m1 - mn1);
        m0 = mn0; m1 = mn1;

        float rs0 = 0.f, rs1 = 0.f;
#pragma unroll
        for (int nt = 0; nt < 8; nt++) {
            float p0 = __expf(s[nt][0] - mn0);
            float p1 = __expf(s[nt][1] - mn0);
            float p2 = __expf(s[nt][2] - mn1);
            float p3 = __expf(s[nt][3] - mn1);
            s[nt][0] = p0; s[nt][1] = p1; s[nt][2] = p2; s[nt][3] = p3;
            rs0 += p0 + p1; rs1 += p2 + p3;
            o[nt][0] *= sc0; o[nt][1] *= sc0;
            o[nt][2] *= sc1; o[nt][3] *= sc1;
        }
        rs0 += __shfl_xor_sync(0xffffffffu, rs0, 1);
        rs0 += __shfl_xor_sync(0xffffffffu, rs0, 2);
        rs1 += __shfl_xor_sync(0xffffffffu, rs1, 1);
        rs1 += __shfl_xor_sync(0xffffffffu, rs1, 2);
        l0s = l0s * sc0 + rs0;
        l1s = l1s * sc1 + rs1;

        // O += P @ V : P A-frags packed directly from S accumulators
#pragma unroll
        for (int kc = 0; kc < 4; kc++) {
            unsigned ph[4], pl[4];
            split2(s[2 * kc    ][0], s[2 * kc    ][1], ph[0], pl[0]);
            split2(s[2 * kc    ][2], s[2 * kc    ][3], ph[1], pl[1]);
            split2(s[2 * kc + 1][0], s[2 * kc + 1][1], ph[2], pl[2]);
            split2(s[2 * kc + 1][2], s[2 * kc + 1][3], ph[3], pl[3]);
#pragma unroll
            for (int nt = 0; nt < 8; nt++) {
                int rd = (nt * 8 + g) * FL_ST + 8 * kc;
                unsigned vh[2], vl[2];
                vh[0] = Vt_hi[rd + t];     vl[0] = Vt_lo[rd + t];
                vh[1] = Vt_hi[rd + 4 + t]; vl[1] = Vt_lo[rd + 4 + t];
                mma16_x3(o[nt], ph, pl, vh, vl);
            }
        }
    }

    // Epilogue
    float inv0 = 1.f / l0s, inv1 = 1.f / l1s;
    int row0 = b * SEQ + qb * 64 + w * 16 + g;
#pragma unroll
    for (int nt = 0; nt < 8; nt++) {
        int col = h * HD + nt * 8 + 2 * t;
        *(float2*)&O[(size_t)row0 * QDIM + col] =
            make_float2(o[nt][0] * inv0, o[nt][1] * inv0);
        *(float2*)&O[(size_t)(row0 + 8) * QDIM + col] =
            make_float2(o[nt][2] * inv1, o[nt][3] * inv1);
    }
}

// ---------------------------------------------------------------------------
extern "C" void kernel_launch(void* const* d_in, const int* in_sizes, int n_in,
                              void* d_out, int out_size)
{
    const float* x  = (const float*)d_in[0];
    const float* Wq = (const float*)d_in[1];
    const float* bq = (const float*)d_in[2];
    const float* Wk = (const float*)d_in[3];
    const float* bk = (const float*)d_in[4];
    const float* Wv = (const float*)d_in[5];
    const float* bv = (const float*)d_in[6];
    const float* Wo = (const float*)d_in[7];
    const float* bo = (const float*)d_in[8];
    float* out = (float*)d_out;

    float *Qp, *Kp, *Vp, *Ap;
    cudaGetSymbolAddress((void**)&Qp, g_Q);
    cudaGetSymbolAddress((void**)&Kp, g_K);
    cudaGetSymbolAddress((void**)&Vp, g_V);
    cudaGetSymbolAddress((void**)&Ap, g_A);

    cudaFuncSetAttribute(flash_gqa_bf16,
                         cudaFuncAttributeMaxDynamicSharedMemorySize, (int)FLASH_SMEM);

    // QKV projections (3xBF16 tensor cores)
    sgemm_bf16x3<<<dim3(QDIM  / 128, MROWS / 128), 256>>>(x, Wq, bq, Qp, MROWS, QDIM,  HIDDEN);
    sgemm_bf16x3<<<dim3(KVDIM / 128, MROWS / 128), 256>>>(x, Wk, bk, Kp, MROWS, KVDIM, HIDDEN);
    sgemm_bf16x3<<<dim3(KVDIM / 128, MROWS / 128), 256>>>(x, Wv, bv, Vp, MROWS, KVDIM, HIDDEN);

    // Flash attention (3xBF16 tensor cores)
    flash_gqa_bf16<<<dim3(SEQ / 64, BATCH * NH), 128, FLASH_SMEM>>>(Qp, Kp, Vp, Ap);

    // Output projection -> d_out
    sgemm_bf16x3<<<dim3(HIDDEN / 128, MROWS / 128), 256>>>(Ap, Wo, bo, out, MROWS, HIDDEN, HIDDEN);
}

// round 14
// speedup vs baseline: 3.7254x; 1.1761x over previous
#include <cuda_runtime.h>
#include <cuda_bf16.h>

#define HIDDEN 1024
#define NH     16
#define NKV    4
#define HD     64
#define BATCH  2
#define SEQ    2048
#define MROWS  (BATCH*SEQ)   // 4096
#define QDIM   (NH*HD)       // 1024
#define KVDIM  (NKV*HD)      // 256

// Scratch (allocation-free rule: __device__ globals)
__device__ float g_Q[MROWS * QDIM];
__device__ float g_K[MROWS * KVDIM];
__device__ float g_V[MROWS * KVDIM];
__device__ float g_A[MROWS * QDIM];

// Pack two floats into one bf162 register (x0 -> low half)
__device__ __forceinline__ unsigned pack2(float x0, float x1) {
    __nv_bfloat162 v = __floats2bfloat162_rn(x0, x1);
    return *(unsigned*)&v;
}

__device__ __forceinline__ unsigned prmt(unsigned a, unsigned b, unsigned s) {
    unsigned r;
    asm("prmt.b32 %0,%1,%2,%3;" : "=r"(r) : "r"(a), "r"(b), "r"(s));
    return r;
}

// Split two floats into bf16 hi-pair (truncation, via PRMT) + bf16 lo-pair
__device__ __forceinline__ void split2(float x0, float x1, unsigned& hi, unsigned& lo) {
    unsigned u0 = __float_as_uint(x0), u1 = __float_as_uint(x1);
    hi = prmt(u0, u1, 0x7632);   // {x1.hi16, x0.hi16}
    float h0 = __uint_as_float(u0 & 0xffff0000u);
    float h1 = __uint_as_float(u1 & 0xffff0000u);
    lo = pack2(x0 - h0, x1 - h1);
}

// ldmatrix x4: 4 8x8 b16 matrices; per-lane address in shared space (bytes)
__device__ __forceinline__ void ldsm4(unsigned& r0, unsigned& r1, unsigned& r2, unsigned& r3,
                                      unsigned saddr) {
    asm volatile("ldmatrix.sync.aligned.m8n8.x4.shared.b16 {%0,%1,%2,%3}, [%4];"
                 : "=r"(r0), "=r"(r1), "=r"(r2), "=r"(r3) : "r"(saddr));
}

// D += A(16x16,row) * B(16x8,col)  bf16, fp32 accum
__device__ __forceinline__ void mma16(float* d, const unsigned* a, const unsigned* b) {
    asm volatile(
        "mma.sync.aligned.m16n8k16.row.col.f32.bf16.bf16.f32 "
        "{%0,%1,%2,%3}, {%4,%5,%6,%7}, {%8,%9}, {%0,%1,%2,%3};\n"
        : "+f"(d[0]), "+f"(d[1]), "+f"(d[2]), "+f"(d[3])
        : "r"(a[0]), "r"(a[1]), "r"(a[2]), "r"(a[3]), "r"(b[0]), "r"(b[1]));
}

// 3xBF16: d += alo*bhi + ahi*blo + ahi*bhi
__device__ __forceinline__ void mma16_x3(float* d, const unsigned* ahi, const unsigned* alo,
                                         const unsigned* bhi, const unsigned* blo) {
    mma16(d, alo, bhi);
    mma16(d, ahi, blo);
    mma16(d, ahi, bhi);
}

// ---------------------------------------------------------------------------
// 3xBF16 GEMM body: C[:,bn..bn+128) += A[bm..bm+128,:] @ B + bias  (K=1024-ish)
// CTA tile 128x128, BK=32, 256 thr = 8 warps (4m x 2n), warp tile 32x64.
// Smem bf162 words, row stride 20 -> LDSM conflict-free (20r mod 32 distinct).
// ---------------------------------------------------------------------------
#define GA_ST 20

__device__ __forceinline__ void gemm_body(
    const float* __restrict__ A, const float* __restrict__ B,
    const float* __restrict__ bias, float* __restrict__ C,
    int N, int K, int bm, int bn,
    unsigned* As_hi, unsigned* As_lo, unsigned* Bs_hi, unsigned* Bs_lo)
{
    const int tid  = threadIdx.x;
    const int warp = tid >> 5, lane = tid & 31;
    const int g = lane >> 2, t = lane & 3;
    const int wm = warp >> 1, wn = warp & 1;
    const int m8 = lane >> 3, r8 = lane & 7;   // ldmatrix lane decomposition

    const unsigned ash = (unsigned)__cvta_generic_to_shared(As_hi);
    const unsigned asl = (unsigned)__cvta_generic_to_shared(As_lo);
    const unsigned bsh = (unsigned)__cvta_generic_to_shared(Bs_hi);
    const unsigned bsl = (unsigned)__cvta_generic_to_shared(Bs_lo);

    float acc[2][8][4];
#pragma unroll
    for (int mt = 0; mt < 2; mt++)
#pragma unroll
        for (int nt = 0; nt < 8; nt++)
#pragma unroll
            for (int i = 0; i < 4; i++) acc[mt][nt][i] = 0.f;

    for (int k0 = 0; k0 < K; k0 += 32) {
        // Stage A tile 128x32: pairs along k
#pragma unroll
        for (int i = 0; i < 4; i++) {
            int id = tid + i * 256;
            int r = id >> 3, c4 = id & 7;
            float4 v = *(const float4*)&A[(size_t)(bm + r) * K + k0 + c4 * 4];
            unsigned h0, l0, h1, l1;
            split2(v.x, v.y, h0, l0);
            split2(v.z, v.w, h1, l1);
            *(uint2*)&As_hi[r * GA_ST + 2 * c4] = make_uint2(h0, h1);
            *(uint2*)&As_lo[r * GA_ST + 2 * c4] = make_uint2(l0, l1);
        }
        // Stage B tile 32x128 transposed: word (n, kp) = {B[k0+2kp][n], B[k0+2kp+1][n]}
#pragma unroll
        for (int i = 0; i < 8; i++) {
            int id = tid + i * 256;
            int n = id & 127, kp = id >> 7;
            float b0 = B[(size_t)(k0 + 2 * kp    ) * N + bn + n];
            float b1 = B[(size_t)(k0 + 2 * kp + 1) * N + bn + n];
            unsigned h, l;
            split2(b0, b1, h, l);
            Bs_hi[n * GA_ST + kp] = h;
            Bs_lo[n * GA_ST + kp] = l;
        }
        __syncthreads();

#pragma unroll
        for (int kc = 0; kc < 2; kc++) {
            unsigned ah[2][4], al[2][4];
#pragma unroll
            for (int mt = 0; mt < 2; mt++) {
                int row = wm * 32 + mt * 16 + ((m8 & 1) << 3) + r8;
                unsigned off = (row * GA_ST + 8 * kc + ((m8 >> 1) << 2)) * 4u;
                ldsm4(ah[mt][0], ah[mt][1], ah[mt][2], ah[mt][3], ash + off);
                ldsm4(al[mt][0], al[mt][1], al[mt][2], al[mt][3], asl + off);
            }
#pragma unroll
            for (int j = 0; j < 4; j++) {
                // 4 matrices = b0,b1 for nt=2j and nt=2j+1
                int row = wn * 64 + ((2 * j + (m8 >> 1)) << 3) + r8;
                unsigned off = (row * GA_ST + 8 * kc + ((m8 & 1) << 2)) * 4u;
                unsigned bh[4], bl[4];
                ldsm4(bh[0], bh[1], bh[2], bh[3], bsh + off);
                ldsm4(bl[0], bl[1], bl[2], bl[3], bsl + off);
#pragma unroll
                for (int mt = 0; mt < 2; mt++) {
                    mma16_x3(acc[mt][2 * j    ], ah[mt], al[mt], bh,     bl);
                    mma16_x3(acc[mt][2 * j + 1], ah[mt], al[mt], bh + 2, bl + 2);
                }
            }
        }
        __syncthreads();
    }

    // Epilogue: c0/c1 at (row g, cols 2t,2t+1), c2/c3 at row g+8
#pragma unroll
    for (int mt = 0; mt < 2; mt++) {
        int row = bm + wm * 32 + mt * 16 + g;
#pragma unroll
        for (int nt = 0; nt < 8; nt++) {
            int col = bn + wn * 64 + nt * 8 + 2 * t;
            float bx = bias[col], by = bias[col + 1];
            float2 o0 = make_float2(acc[mt][nt][0] + bx, acc[mt][nt][1] + by);
            float2 o1 = make_float2(acc[mt][nt][2] + bx, acc[mt][nt][3] + by);
            *(float2*)&C[(size_t)row * N + col]       = o0;
            *(float2*)&C[(size_t)(row + 8) * N + col] = o1;
        }
    }
}

// Fused QKV projection: grid (12, MROWS/128). n-blocks 0-7 -> Q, 8-9 -> K, 10-11 -> V.
__global__ __launch_bounds__(256, 2) void gemm_qkv(
    const float* __restrict__ x,
    const float* __restrict__ Wq, const float* __restrict__ bq,
    const float* __restrict__ Wk, const float* __restrict__ bk,
    const float* __restrict__ Wv, const float* __restrict__ bv,
    float* __restrict__ Qp, float* __restrict__ Kp, float* __restrict__ Vp)
{
    __shared__ unsigned As_hi[128 * GA_ST], As_lo[128 * GA_ST];
    __shared__ unsigned Bs_hi[128 * GA_ST], Bs_lo[128 * GA_ST];

    int bnb = blockIdx.x;
    const float *B, *bias; float* C; int N, bn;
    if (bnb < 8)       { B = Wq; bias = bq; C = Qp; N = QDIM;  bn = bnb * 128; }
    else if (bnb < 10) { B = Wk; bias = bk; C = Kp; N = KVDIM; bn = (bnb - 8) * 128; }
    else               { B = Wv; bias = bv; C = Vp; N = KVDIM; bn = (bnb - 10) * 128; }

    gemm_body(x, B, bias, C, N, HIDDEN, blockIdx.y * 128, bn,
              As_hi, As_lo, Bs_hi, Bs_lo);
}

// Plain GEMM (O projection): grid (N/128, M/128)
__global__ __launch_bounds__(256, 2) void gemm_plain(
    const float* __restrict__ A, const float* __restrict__ B,
    const float* __restrict__ bias, float* __restrict__ C, int N, int K)
{
    __shared__ unsigned As_hi[128 * GA_ST], As_lo[128 * GA_ST];
    __shared__ unsigned Bs_hi[128 * GA_ST], Bs_lo[128 * GA_ST];
    gemm_body(A, B, bias, C, N, K, blockIdx.y * 128, blockIdx.x * 128,
              As_hi, As_lo, Bs_hi, Bs_lo);
}

// ---------------------------------------------------------------------------
// Flash GQA attention, 3xBF16 + ldmatrix (NO 1/sqrt(d) scaling, no mask).
// Grid: (SEQ/64, BATCH*NH). 128 threads = 4 warps; warp w owns q-rows
// [w*16, w*16+16). 64-key tiles; P stays in registers.
// Dynamic smem: Qs,Ks,Vt x (hi,lo), each 64 x 36 words = 55296 bytes.
// ---------------------------------------------------------------------------
#define FL_ST 36   // 36r mod 32 = 4r -> LDSM conflict-free
#define FLASH_SMEM (6 * 64 * FL_ST * sizeof(unsigned))

__global__ __launch_bounds__(128, 4) void flash_gqa_bf16(
    const float* __restrict__ Q, const float* __restrict__ K,
    const float* __restrict__ V, float* __restrict__ O)
{
    extern __shared__ unsigned smu[];
    unsigned* Qs_hi = smu;                      // [qrow][dpair]
    unsigned* Qs_lo = Qs_hi + 64 * FL_ST;
    unsigned* Ks_hi = Qs_lo + 64 * FL_ST;       // [key][dpair]
    unsigned* Ks_lo = Ks_hi + 64 * FL_ST;
    unsigned* Vt_hi = Ks_lo + 64 * FL_ST;       // [d][keypair] (transposed)
    unsigned* Vt_lo = Vt_hi + 64 * FL_ST;

    const unsigned qsh = (unsigned)__cvta_generic_to_shared(Qs_hi);
    const unsigned qsl = (unsigned)__cvta_generic_to_shared(Qs_lo);
    const unsigned ksh = (unsigned)__cvta_generic_to_shared(Ks_hi);
    const unsigned ksl = (unsigned)__cvta_generic_to_shared(Ks_lo);
    const unsigned vth = (unsigned)__cvta_generic_to_shared(Vt_hi);
    const unsigned vtl = (unsigned)__cvta_generic_to_shared(Vt_lo);

    const int tid = threadIdx.x;
    const int w = tid >> 5, lane = tid & 31;
    const int m8 = lane >> 3, r8 = lane & 7;
    const int g = lane >> 2, t = lane & 3;
    const int qb = blockIdx.x;
    const int bh = blockIdx.y;
    const int b = bh >> 4, h = bh & 15, kh = h >> 2;

    const float* Qb = Q + (size_t)b * SEQ * QDIM  + h  * HD;
    const float* Kb = K + (size_t)b * SEQ * KVDIM + kh * HD;
    const float* Vb = V + (size_t)b * SEQ * KVDIM + kh * HD;

    // Stage Q tile (64x64) as bf16 hi/lo pairs along d
#pragma unroll
    for (int i = 0; i < 8; i++) {
        int id = tid + i * 128;
        int r = id >> 4, c4 = id & 15;
        float4 v = *(const float4*)&Qb[(size_t)(qb * 64 + r) * QDIM + c4 * 4];
        unsigned h0, l0, h1, l1;
        split2(v.x, v.y, h0, l0);
        split2(v.z, v.w, h1, l1);
        *(uint2*)&Qs_hi[r * FL_ST + 2 * c4] = make_uint2(h0, h1);
        *(uint2*)&Qs_lo[r * FL_ST + 2 * c4] = make_uint2(l0, l1);
    }

    float o[8][4];
#pragma unroll
    for (int nt = 0; nt < 8; nt++)
#pragma unroll
        for (int i = 0; i < 4; i++) o[nt][i] = 0.f;
    float m0 = -1e30f, m1 = -1e30f, l0s = 0.f, l1s = 0.f;

    for (int kb = 0; kb < SEQ / 64; kb++) {
        __syncthreads();   // prev-tile consumers done (also orders Q staging on kb=0)
        // Stage K tile (pairs along d)
#pragma unroll
        for (int i = 0; i < 8; i++) {
            int id = tid + i * 128;
            int r = id >> 4, c4 = id & 15;
            float4 kv = *(const float4*)&Kb[(size_t)(kb * 64 + r) * KVDIM + c4 * 4];
            unsigned h0, l0, h1, l1;
            split2(kv.x, kv.y, h0, l0);
            split2(kv.z, kv.w, h1, l1);
            *(uint2*)&Ks_hi[r * FL_ST + 2 * c4] = make_uint2(h0, h1);
            *(uint2*)&Ks_lo[r * FL_ST + 2 * c4] = make_uint2(l0, l1);
        }
        // Stage V transposed: word (d, kp) = {V[2kp][d], V[2kp+1][d]}
#pragma unroll
        for (int i = 0; i < 16; i++) {
            int id = tid + i * 128;
            int kp = id >> 6, d = id & 63;
            float v0 = Vb[(size_t)(kb * 64 + 2 * kp    ) * KVDIM + d];
            float v1 = Vb[(size_t)(kb * 64 + 2 * kp + 1) * KVDIM + d];
            unsigned hh, ll;
            split2(v0, v1, hh, ll);
            Vt_hi[d * FL_ST + kp] = hh;
            Vt_lo[d * FL_ST + kp] = ll;
        }
        __syncthreads();

        // S = Q @ K^T : 8 n-tiles of 16x8, K-dim in 4 chunks of 16
        float s[8][4];
#pragma unroll
        for (int nt = 0; nt < 8; nt++)
#pragma unroll
            for (int i = 0; i < 4; i++) s[nt][i] = 0.f;

#pragma unroll
        for (int kc = 0; kc < 4; kc++) {
            unsigned qh[4], ql[4];
            {
                int row = w * 16 + ((m8 & 1) << 3) + r8;
                unsigned off = (row * FL_ST + 8 * kc + ((m8 >> 1) << 2)) * 4u;
                ldsm4(qh[0], qh[1], qh[2], qh[3], qsh + off);
                ldsm4(ql[0], ql[1], ql[2], ql[3], qsl + off);
            }
#pragma unroll
            for (int j = 0; j < 4; j++) {
                int row = ((2 * j + (m8 >> 1)) << 3) + r8;
                unsigned off = (row * FL_ST + 8 * kc + ((m8 & 1) << 2)) * 4u;
                unsigned bh_[4], bl_[4];
                ldsm4(bh_[0], bh_[1], bh_[2], bh_[3], ksh + off);
                ldsm4(bl_[0], bl_[1], bl_[2], bl_[3], ksl + off);
                mma16_x3(s[2 * j    ], qh, ql, bh_,     bl_);
                mma16_x3(s[2 * j + 1], qh, ql, bh_ + 2, bl_ + 2);
            }
        }

        // Online softmax: rows g (regs 0,1) and g+8 (regs 2,3)
        float mx0 = -1e30f, mx1 = -1e30f;
#pragma unroll
        for (int nt = 0; nt < 8; nt++) {
            mx0 = fmaxf(mx0, fmaxf(s[nt][0], s[nt][1]));
            mx1 = fmaxf(mx1, fmaxf(s[nt][2], s[nt][3]));
        }
        mx0 = fmaxf(mx0, __shfl_xor_sync(0xffffffffu, mx0, 1));
        mx0 = fmaxf(mx0, __shfl_xor_sync(0xffffffffu, mx0, 2));
        mx1 = fmaxf(mx1, __shfl_xor_sync(0xffffffffu, mx1, 1));
        mx1 = fmaxf(mx1, __shfl_xor_sync(0xffffffffu, mx1, 2));

        float mn0 = fmaxf(m0, mx0), mn1 = fmaxf(m1, mx1);
        float sc0 = __expf(m0 - mn0), sc1 = __expf(m1 - mn1);
        m0 = mn0; m1 = mn1;

        float rs0 = 0.f, rs1 = 0.f;
#pragma unroll
        for (int nt = 0; nt < 8; nt++) {
            float p0 = __expf(s[nt][0] - mn0);
            float p1 = __expf(s[nt][1] - mn0);
            float p2 = __expf(s[nt][2] - mn1);
            float p3 = __expf(s[nt][3] - mn1);
            s[nt][0] = p0; s[nt][1] = p1; s[nt][2] = p2; s[nt][3] = p3;
            rs0 += p0 + p1; rs1 += p2 + p3;
            o[nt][0] *= sc0; o[nt][1] *= sc0;
            o[nt][2] *= sc1; o[nt][3] *= sc1;
        }
        rs0 += __shfl_xor_sync(0xffffffffu, rs0, 1);
        rs0 += __shfl_xor_sync(0xffffffffu, rs0, 2);
        rs1 += __shfl_xor_sync(0xffffffffu, rs1, 1);
        rs1 += __shfl_xor_sync(0xffffffffu, rs1, 2);
        l0s = l0s * sc0 + rs0;
        l1s = l1s * sc1 + rs1;

        // O += P @ V : P A-frags packed directly from S accumulators
#pragma unroll
        for (int kc = 0; kc < 4; kc++) {
            unsigned ph[4], pl[4];
            split2(s[2 * kc    ][0], s[2 * kc    ][1], ph[0], pl[0]);
            split2(s[2 * kc    ][2], s[2 * kc    ][3], ph[1], pl[1]);
            split2(s[2 * kc + 1][0], s[2 * kc + 1][1], ph[2], pl[2]);
            split2(s[2 * kc + 1][2], s[2 * kc + 1][3], ph[3], pl[3]);
#pragma unroll
            for (int j = 0; j < 4; j++) {
                int row = ((2 * j + (m8 >> 1)) << 3) + r8;
                unsigned off = (row * FL_ST + 8 * kc + ((m8 & 1) << 2)) * 4u;
                unsigned vh[4], vl[4];
                ldsm4(vh[0], vh[1], vh[2], vh[3], vth + off);
                ldsm4(vl[0], vl[1], vl[2], vl[3], vtl + off);
                mma16_x3(o[2 * j    ], ph, pl, vh,     vl);
                mma16_x3(o[2 * j + 1], ph, pl, vh + 2, vl + 2);
            }
        }
    }

    // Epilogue
    float inv0 = 1.f / l0s, inv1 = 1.f / l1s;
    int row0 = b * SEQ + qb * 64 + w * 16 + g;
#pragma unroll
    for (int nt = 0; nt < 8; nt++) {
        int col = h * HD + nt * 8 + 2 * t;
        *(float2*)&O[(size_t)row0 * QDIM + col] =
            make_float2(o[nt][0] * inv0, o[nt][1] * inv0);
        *(float2*)&O[(size_t)(row0 + 8) * QDIM + col] =
            make_float2(o[nt][2] * inv1, o[nt][3] * inv1);
    }
}

// ---------------------------------------------------------------------------
extern "C" void kernel_launch(void* const* d_in, const int* in_sizes, int n_in,
                              void* d_out, int out_size)
{
    const float* x  = (const float*)d_in[0];
    const float* Wq = (const float*)d_in[1];
    const float* bq = (const float*)d_in[2];
    const float* Wk = (const float*)d_in[3];
    const float* bk = (const float*)d_in[4];
    const float* Wv = (const float*)d_in[5];
    const float* bv = (const float*)d_in[6];
    const float* Wo = (const float*)d_in[7];
    const float* bo = (const float*)d_in[8];
    float* out = (float*)d_out;

    float *Qp, *Kp, *Vp, *Ap;
    cudaGetSymbolAddress((void**)&Qp, g_Q);
    cudaGetSymbolAddress((void**)&Kp, g_K);
    cudaGetSymbolAddress((void**)&Vp, g_V);
    cudaGetSymbolAddress((void**)&Ap, g_A);

    cudaFuncSetAttribute(flash_gqa_bf16,
                         cudaFuncAttributeMaxDynamicSharedMemorySize, (int)FLASH_SMEM);

    // Fused QKV projection (3xBF16 tensor cores, full-chip grid)
    gemm_qkv<<<dim3(12, MROWS / 128), 256>>>(x, Wq, bq, Wk, bk, Wv, bv, Qp, Kp, Vp);

    // Flash attention (3xBF16 + ldmatrix)
    flash_gqa_bf16<<<dim3(SEQ / 64, BATCH * NH), 128, FLASH_SMEM>>>(Qp, Kp, Vp, Ap);

    // Output projection -> d_out
    gemm_plain<<<dim3(HIDDEN / 128, MROWS / 128), 256>>>(Ap, Wo, bo, out, HIDDEN, HIDDEN);
}

// round 16
// speedup vs baseline: 4.1041x; 1.1017x over previous
#include <cuda_runtime.h>
#include <cuda_bf16.h>

#define HIDDEN 1024
#define NH     16
#define NKV    4
#define HD     64
#define BATCH  2
#define SEQ    2048
#define MROWS  (BATCH*SEQ)   // 4096
#define QDIM   (NH*HD)       // 1024
#define KVDIM  (NKV*HD)      // 256

// ---------------------------------------------------------------------------
// Packed bf16 hi/lo scratch (pairs along the K/contraction dim), device globals
// ---------------------------------------------------------------------------
__device__ unsigned g_Xh[MROWS * 512],  g_Xl[MROWS * 512];    // x packed [row][hpair]
__device__ unsigned g_Wqh[QDIM * 512],  g_Wql[QDIM * 512];    // W^T packed [n][kpair]
__device__ unsigned g_Wkh[KVDIM * 512], g_Wkl[KVDIM * 512];
__device__ unsigned g_Wvh[KVDIM * 512], g_Wvl[KVDIM * 512];
__device__ unsigned g_Woh[HIDDEN * 512], g_Wol[HIDDEN * 512];
__device__ unsigned g_Qh[MROWS * 512],  g_Ql[MROWS * 512];    // Q packed [row][dpair]
__device__ unsigned g_Kh[MROWS * 128],  g_Kl[MROWS * 128];    // K packed [row][dpair]
__device__ unsigned g_Vh[MROWS * 128],  g_Vl[MROWS * 128];    // V packed [row][dpair]
__device__ unsigned g_Ah[MROWS * 512],  g_Al[MROWS * 512];    // attn out packed

// ---------------------------------------------------------------------------
// Helpers
// ---------------------------------------------------------------------------
__device__ __forceinline__ unsigned pack2(float x0, float x1) {
    __nv_bfloat162 v = __floats2bfloat162_rn(x0, x1);
    return *(unsigned*)&v;
}
__device__ __forceinline__ unsigned prmt(unsigned a, unsigned b, unsigned s) {
    unsigned r;
    asm("prmt.b32 %0,%1,%2,%3;" : "=r"(r) : "r"(a), "r"(b), "r"(s));
    return r;
}
// bf16 hi (truncation) + bf16 lo residual
__device__ __forceinline__ void split2(float x0, float x1, unsigned& hi, unsigned& lo) {
    unsigned u0 = __float_as_uint(x0), u1 = __float_as_uint(x1);
    hi = prmt(u0, u1, 0x7632);
    float h0 = __uint_as_float(u0 & 0xffff0000u);
    float h1 = __uint_as_float(u1 & 0xffff0000u);
    lo = pack2(x0 - h0, x1 - h1);
}
__device__ __forceinline__ void ldsm4(unsigned& r0, unsigned& r1, unsigned& r2, unsigned& r3,
                                      unsigned saddr) {
    asm volatile("ldmatrix.sync.aligned.m8n8.x4.shared.b16 {%0,%1,%2,%3}, [%4];"
                 : "=r"(r0), "=r"(r1), "=r"(r2), "=r"(r3) : "r"(saddr));
}
__device__ __forceinline__ void ldsm4t(unsigned& r0, unsigned& r1, unsigned& r2, unsigned& r3,
                                       unsigned saddr) {
    asm volatile("ldmatrix.sync.aligned.m8n8.x4.trans.shared.b16 {%0,%1,%2,%3}, [%4];"
                 : "=r"(r0), "=r"(r1), "=r"(r2), "=r"(r3) : "r"(saddr));
}
__device__ __forceinline__ void cpasync16(unsigned dst_s, const void* src) {
    asm volatile("cp.async.ca.shared.global [%0], [%1], 16;" :: "r"(dst_s), "l"(src));
}
#define CP_COMMIT() asm volatile("cp.async.commit_group;")
#define CP_WAIT1()  asm volatile("cp.async.wait_group 1;")
#define CP_WAIT0()  asm volatile("cp.async.wait_group 0;")

__device__ __forceinline__ void mma16(float* d, const unsigned* a, const unsigned* b) {
    asm volatile(
        "mma.sync.aligned.m16n8k16.row.col.f32.bf16.bf16.f32 "
        "{%0,%1,%2,%3}, {%4,%5,%6,%7}, {%8,%9}, {%0,%1,%2,%3};\n"
        : "+f"(d[0]), "+f"(d[1]), "+f"(d[2]), "+f"(d[3])
        : "r"(a[0]), "r"(a[1]), "r"(a[2]), "r"(a[3]), "r"(b[0]), "r"(b[1]));
}
__device__ __forceinline__ void mma16_x3(float* d, const unsigned* ahi, const unsigned* alo,
                                         const unsigned* bhi, const unsigned* blo) {
    mma16(d, alo, bhi);
    mma16(d, ahi, blo);
    mma16(d, ahi, bhi);
}

// ---------------------------------------------------------------------------
// Pack kernels (run once per launch; tiny)
// ---------------------------------------------------------------------------
__global__ void pack_x(const float* __restrict__ x,
                       unsigned* __restrict__ Xh, unsigned* __restrict__ Xl) {
    int id = blockIdx.x * 256 + threadIdx.x;          // over MROWS*512 words
    float2 v = *(const float2*)&x[(size_t)id * 2];
    unsigned h, l;
    split2(v.x, v.y, h, l);
    Xh[id] = h; Xl[id] = l;
}

// W [K=1024][N] row-major -> packed [N][K/2=512] (pairs along K). Tiled transpose.
__global__ void pack_w(const float* __restrict__ W,
                       unsigned* __restrict__ Oh, unsigned* __restrict__ Ol, int N) {
    __shared__ float tile[64][33];
    int k0 = blockIdx.x * 64, n0 = blockIdx.y * 32;
    int tid = threadIdx.x;
#pragma unroll
    for (int i = 0; i < 8; i++) {
        int id = tid + i * 256;
        int n = id & 31, k = id >> 5;
        tile[k][n] = W[(size_t)(k0 + k) * N + n0 + n];
    }
    __syncthreads();
#pragma unroll
    for (int i = 0; i < 4; i++) {
        int id = tid + i * 256;
        int kp = id & 31, n = id >> 5;
        unsigned h, l;
        split2(tile[2 * kp][n], tile[2 * kp + 1][n], h, l);
        Oh[(size_t)(n0 + n) * 512 + k0 / 2 + kp] = h;
        Ol[(size_t)(n0 + n) * 512 + k0 / 2 + kp] = l;
    }
}

// ---------------------------------------------------------------------------
// 3xBF16 GEMM on packed operands, cp.async double-buffered. K=1024 fixed.
// CTA tile 128x128, BK=32, 256 thr = 8 warps (4m x 2n), warp tile 32x64.
// Smem stage: Ah|Al|Bh|Bl each 128x20 words (16 used) = 40960 B; x2 stages.
// EPI: 0 = fp32 C + bias; 1 = packed bf16 hi/lo out + bias.
// All pointers un-offset; bm/bn do ALL the offsetting (A rows, B rows, bias,
// and output columns are global indices).
// ---------------------------------------------------------------------------
#define GA_ST 20
#define GEMM_SMEM (2 * 4 * 128 * GA_ST * sizeof(unsigned))   // 81920

template<int EPI>
__device__ __forceinline__ void gemm_body(
    const unsigned* __restrict__ Ah, const unsigned* __restrict__ Al,
    const unsigned* __restrict__ Bh, const unsigned* __restrict__ Bl,
    const float* __restrict__ bias,
    float* __restrict__ C, unsigned* __restrict__ Oh, unsigned* __restrict__ Ol,
    int out_ld, int bm, int bn, unsigned* smem)
{
    const int tid  = threadIdx.x;
    const int warp = tid >> 5, lane = tid & 31;
    const int g = lane >> 2, t = lane & 3;
    const int wm = warp >> 1, wn = warp & 1;
    const int m8 = lane >> 3, r8 = lane & 7;
    const unsigned sb0 = (unsigned)__cvta_generic_to_shared(smem);

    auto stage = [&](int kt, int s) {
        unsigned sb = sb0 + s * 40960;
#pragma unroll
        for (int i = 0; i < 2; i++) {
            int id = tid * 2 + i;
            int r = id >> 2, c = id & 3;
            unsigned doff = (r * GA_ST + c * 4) * 4u;
            size_t ga = (size_t)(bm + r) * 512 + kt * 16 + c * 4;
            size_t gb = (size_t)(bn + r) * 512 + kt * 16 + c * 4;
            cpasync16(sb +         doff, Ah + ga);
            cpasync16(sb + 10240 + doff, Al + ga);
            cpasync16(sb + 20480 + doff, Bh + gb);
            cpasync16(sb + 30720 + doff, Bl + gb);
        }
    };

    float acc[2][8][4];
#pragma unroll
    for (int mt = 0; mt < 2; mt++)
#pragma unroll
        for (int nt = 0; nt < 8; nt++)
#pragma unroll
            for (int i = 0; i < 4; i++) acc[mt][nt][i] = 0.f;

    stage(0, 0);
    CP_COMMIT();

    for (int kt = 0; kt < 32; kt++) {
        if (kt + 1 < 32) {
            stage(kt + 1, (kt + 1) & 1);
            CP_COMMIT();
            CP_WAIT1();
        } else {
            CP_WAIT0();
        }
        __syncthreads();

        unsigned sb = sb0 + (kt & 1) * 40960;
        const unsigned ash = sb, asl = sb + 10240, bsh = sb + 20480, bsl = sb + 30720;
#pragma unroll
        for (int kc = 0; kc < 2; kc++) {
            unsigned ah[2][4], al[2][4];
#pragma unroll
            for (int mt = 0; mt < 2; mt++) {
                int row = wm * 32 + mt * 16 + ((m8 & 1) << 3) + r8;
                unsigned off = (row * GA_ST + 8 * kc + ((m8 >> 1) << 2)) * 4u;
                ldsm4(ah[mt][0], ah[mt][1], ah[mt][2], ah[mt][3], ash + off);
                ldsm4(al[mt][0], al[mt][1], al[mt][2], al[mt][3], asl + off);
            }
#pragma unroll
            for (int j = 0; j < 4; j++) {
                int row = wn * 64 + ((2 * j + (m8 >> 1)) << 3) + r8;
                unsigned off = (row * GA_ST + 8 * kc + ((m8 & 1) << 2)) * 4u;
                unsigned bh[4], bl[4];
                ldsm4(bh[0], bh[1], bh[2], bh[3], bsh + off);
                ldsm4(bl[0], bl[1], bl[2], bl[3], bsl + off);
#pragma unroll
                for (int mt = 0; mt < 2; mt++) {
                    mma16_x3(acc[mt][2 * j    ], ah[mt], al[mt], bh,     bl);
                    mma16_x3(acc[mt][2 * j + 1], ah[mt], al[mt], bh + 2, bl + 2);
                }
            }
        }
        __syncthreads();
    }

    // Epilogue
#pragma unroll
    for (int mt = 0; mt < 2; mt++) {
        int row = bm + wm * 32 + mt * 16 + g;
#pragma unroll
        for (int nt = 0; nt < 8; nt++) {
            int col = bn + wn * 64 + nt * 8 + 2 * t;   // global output column
            float bx = bias[col], by = bias[col + 1];
            float a0 = acc[mt][nt][0] + bx, a1 = acc[mt][nt][1] + by;
            float a2 = acc[mt][nt][2] + bx, a3 = acc[mt][nt][3] + by;
            if (EPI == 0) {
                *(float2*)&C[(size_t)row * 1024 + col]       = make_float2(a0, a1);
                *(float2*)&C[(size_t)(row + 8) * 1024 + col] = make_float2(a2, a3);
            } else {
                unsigned h, l;
                split2(a0, a1, h, l);
                Oh[(size_t)row * out_ld + (col >> 1)] = h;
                Ol[(size_t)row * out_ld + (col >> 1)] = l;
                split2(a2, a3, h, l);
                Oh[(size_t)(row + 8) * out_ld + (col >> 1)] = h;
                Ol[(size_t)(row + 8) * out_ld + (col >> 1)] = l;
            }
        }
    }
}

// Fused QKV projection: grid (12, 32). n-blocks 0-7 -> Q, 8-9 -> K, 10-11 -> V.
// NOTE: weight/bias pointers passed UN-OFFSET; gemm_body's bn does the offsetting.
__global__ __launch_bounds__(256, 2) void gemm_qkv_b(
    const float* __restrict__ bq, const float* __restrict__ bk, const float* __restrict__ bv)
{
    extern __shared__ unsigned smg[];
    int bnb = blockIdx.x;
    if (bnb < 8) {
        gemm_body<1>(g_Xh, g_Xl, g_Wqh, g_Wql,
                     bq, nullptr, g_Qh, g_Ql, 512, blockIdx.y * 128, bnb * 128, smg);
    } else if (bnb < 10) {
        gemm_body<1>(g_Xh, g_Xl, g_Wkh, g_Wkl,
                     bk, nullptr, g_Kh, g_Kl, 128, blockIdx.y * 128, (bnb - 8) * 128, smg);
    } else {
        gemm_body<1>(g_Xh, g_Xl, g_Wvh, g_Wvl,
                     bv, nullptr, g_Vh, g_Vl, 128, blockIdx.y * 128, (bnb - 10) * 128, smg);
    }
}

// O-projection: grid (8, 32), fp32 out + bias
__global__ __launch_bounds__(256, 2) void gemm_oproj(
    const float* __restrict__ bo, float* __restrict__ out)
{
    extern __shared__ unsigned smg[];
    gemm_body<0>(g_Ah, g_Al, g_Woh, g_Wol, bo, out, nullptr, nullptr, 0,
                 blockIdx.y * 128, blockIdx.x * 128, smg);
}

// ---------------------------------------------------------------------------
// Flash GQA attention, 3xBF16, packed inputs, cp.async double-buffered KV,
// ldmatrix.trans for V. Grid (32, 32), 128 threads = 4 warps.
// Smem: 2 stages x {Kh,Kl,Vh,Vl}[64x36 words] = 73728 B. No Q smem.
// ---------------------------------------------------------------------------
#define FL_ST 36
#define FLASH_SMEM (2 * 4 * 64 * FL_ST * sizeof(unsigned))   // 73728

__global__ __launch_bounds__(128, 3) void flash_gqa(
    const unsigned* __restrict__ Qh, const unsigned* __restrict__ Ql,
    const unsigned* __restrict__ Kh, const unsigned* __restrict__ Kl,
    const unsigned* __restrict__ Vh, const unsigned* __restrict__ Vl,
    unsigned* __restrict__ Ah, unsigned* __restrict__ Al)
{
    extern __shared__ unsigned smu[];
    const unsigned sb0 = (unsigned)__cvta_generic_to_shared(smu);

    const int tid = threadIdx.x;
    const int w = tid >> 5, lane = tid & 31;
    const int m8 = lane >> 3, r8 = lane & 7;
    const int g = lane >> 2, t = lane & 3;
    const int qb = blockIdx.x;
    const int bh = blockIdx.y;
    const int b = bh >> 4, h = bh & 15, kh = h >> 2;
    const int khw = kh * 32;

    auto stageKV = [&](int kb, int s) {
        unsigned sb = sb0 + s * 36864;
        size_t rowbase = (size_t)(b * SEQ + kb * 64);
#pragma unroll
        for (int i = 0; i < 4; i++) {
            int id = tid + i * 128;
            int r = id >> 3, c = id & 7;
            unsigned doff = (r * FL_ST + c * 4) * 4u;
            size_t go = (rowbase + r) * 128 + khw + c * 4;
            cpasync16(sb +         doff, Kh + go);
            cpasync16(sb +  9216 + doff, Kl + go);
            cpasync16(sb + 18432 + doff, Vh + go);
            cpasync16(sb + 27648 + doff, Vl + go);
        }
    };

    stageKV(0, 0);
    CP_COMMIT();

    // Q fragments direct from packed gmem into persistent registers
    unsigned qh[4][4], ql[4][4];
    {
        size_t r0 = (size_t)(b * SEQ + qb * 64 + w * 16 + g) * 512 + h * 32;
        size_t r1 = r0 + 8 * 512;
#pragma unroll
        for (int kc = 0; kc < 4; kc++) {
            qh[kc][0] = Qh[r0 + 8 * kc + t];     ql[kc][0] = Ql[r0 + 8 * kc + t];
            qh[kc][1] = Qh[r1 + 8 * kc + t];     ql[kc][1] = Ql[r1 + 8 * kc + t];
            qh[kc][2] = Qh[r0 + 8 * kc + 4 + t]; ql[kc][2] = Ql[r0 + 8 * kc + 4 + t];
            qh[kc][3] = Qh[r1 + 8 * kc + 4 + t]; ql[kc][3] = Ql[r1 + 8 * kc + 4 + t];
        }
    }

    float o[8][4];
#pragma unroll
    for (int nt = 0; nt < 8; nt++)
#pragma unroll
        for (int i = 0; i < 4; i++) o[nt][i] = 0.f;
    float m0 = -1e30f, m1 = -1e30f, l0s = 0.f, l1s = 0.f;

    for (int kb = 0; kb < SEQ / 64; kb++) {
        if (kb + 1 < SEQ / 64) {
            stageKV(kb + 1, (kb + 1) & 1);
            CP_COMMIT();
            CP_WAIT1();
        } else {
            CP_WAIT0();
        }
        __syncthreads();

        unsigned sb = sb0 + (kb & 1) * 36864;
        const unsigned ksh = sb, ksl = sb + 9216, vth = sb + 18432, vtl = sb + 27648;

        // S = Q @ K^T
        float s[8][4];
#pragma unroll
        for (int nt = 0; nt < 8; nt++)
#pragma unroll
            for (int i = 0; i < 4; i++) s[nt][i] = 0.f;

#pragma unroll
        for (int kc = 0; kc < 4; kc++) {
#pragma unroll
            for (int j = 0; j < 4; j++) {
                int row = ((2 * j + (m8 >> 1)) << 3) + r8;
                unsigned off = (row * FL_ST + 8 * kc + ((m8 & 1) << 2)) * 4u;
                unsigned bh_[4], bl_[4];
                ldsm4(bh_[0], bh_[1], bh_[2], bh_[3], ksh + off);
                ldsm4(bl_[0], bl_[1], bl_[2], bl_[3], ksl + off);
                mma16_x3(s[2 * j    ], qh[kc], ql[kc], bh_,     bl_);
                mma16_x3(s[2 * j + 1], qh[kc], ql[kc], bh_ + 2, bl_ + 2);
            }
        }

        // Online softmax (rows g -> regs 0,1; rows g+8 -> regs 2,3)
        float mx0 = -1e30f, mx1 = -1e30f;
#pragma unroll
        for (int nt = 0; nt < 8; nt++) {
            mx0 = fmaxf(mx0, fmaxf(s[nt][0], s[nt][1]));
            mx1 = fmaxf(mx1, fmaxf(s[nt][2], s[nt][3]));
        }
        mx0 = fmaxf(mx0, __shfl_xor_sync(0xffffffffu, mx0, 1));
        mx0 = fmaxf(mx0, __shfl_xor_sync(0xffffffffu, mx0, 2));
        mx1 = fmaxf(mx1, __shfl_xor_sync(0xffffffffu, mx1, 1));
        mx1 = fmaxf(mx1, __shfl_xor_sync(0xffffffffu, mx1, 2));

        float mn0 = fmaxf(m0, mx0), mn1 = fmaxf(m1, mx1);
        float sc0 = __expf(m0 - mn0), sc1 = __expf(m1 - mn1);
        m0 = mn0; m1 = mn1;

        float rs0 = 0.f, rs1 = 0.f;
#pragma unroll
        for (int nt = 0; nt < 8; nt++) {
            float p0 = __expf(s[nt][0] - mn0);
            float p1 = __expf(s[nt][1] - mn0);
            float p2 = __expf(s[nt][2] - mn1);
            float p3 = __expf(s[nt][3] - mn1);
            s[nt][0] = p0; s[nt][1] = p1; s[nt][2] = p2; s[nt][3] = p3;
            rs0 += p0 + p1; rs1 += p2 + p3;
            o[nt][0] *= sc0; o[nt][1] *= sc0;
            o[nt][2] *= sc1; o[nt][3] *= sc1;
        }
        rs0 += __shfl_xor_sync(0xffffffffu, rs0, 1);
        rs0 += __shfl_xor_sync(0xffffffffu, rs0, 2);
        rs1 += __shfl_xor_sync(0xffffffffu, rs1, 1);
        rs1 += __shfl_xor_sync(0xffffffffu, rs1, 2);
        l0s = l0s * sc0 + rs0;
        l1s = l1s * sc1 + rs1;

        // O += P @ V : P A-frags from S regs; V B-frags via ldmatrix.trans
#pragma unroll
        for (int kc = 0; kc < 4; kc++) {
            unsigned ph[4], pl[4];
            split2(s[2 * kc    ][0], s[2 * kc    ][1], ph[0], pl[0]);
            split2(s[2 * kc    ][2], s[2 * kc    ][3], ph[1], pl[1]);
            split2(s[2 * kc + 1][0], s[2 * kc + 1][1], ph[2], pl[2]);
            split2(s[2 * kc + 1][2], s[2 * kc + 1][3], ph[3], pl[3]);
#pragma unroll
            for (int j = 0; j < 4; j++) {
                int key = kc * 16 + ((m8 & 1) << 3) + r8;
                unsigned off = (key * FL_ST + 8 * j + ((m8 >> 1) << 2)) * 4u;
                unsigned vh[4], vl[4];
                ldsm4t(vh[0], vh[1], vh[2], vh[3], vth + off);
                ldsm4t(vl[0], vl[1], vl[2], vl[3], vtl + off);
                mma16_x3(o[2 * j    ], ph, pl, vh,     vl);
                mma16_x3(o[2 * j + 1], ph, pl, vh + 2, vl + 2);
            }
        }
        __syncthreads();
    }

    // Epilogue: write packed pairs along d
    float inv0 = 1.f / l0s, inv1 = 1.f / l1s;
    size_t row0 = (size_t)(b * SEQ + qb * 64 + w * 16 + g);
#pragma unroll
    for (int nt = 0; nt < 8; nt++) {
        int wcol = h * 32 + nt * 4 + t;
        unsigned hh, ll;
        split2(o[nt][0] * inv0, o[nt][1] * inv0, hh, ll);
        Ah[row0 * 512 + wcol] = hh; Al[row0 * 512 + wcol] = ll;
        split2(o[nt][2] * inv1, o[nt][3] * inv1, hh, ll);
        Ah[(row0 + 8) * 512 + wcol] = hh; Al[(row0 + 8) * 512 + wcol] = ll;
    }
}

// ---------------------------------------------------------------------------
extern "C" void kernel_launch(void* const* d_in, const int* in_sizes, int n_in,
                              void* d_out, int out_size)
{
    const float* x  = (const float*)d_in[0];
    const float* Wq = (const float*)d_in[1];
    const float* bq = (const float*)d_in[2];
    const float* Wk = (const float*)d_in[3];
    const float* bk = (const float*)d_in[4];
    const float* Wv = (const float*)d_in[5];
    const float* bv = (const float*)d_in[6];
    const float* Wo = (const float*)d_in[7];
    const float* bo = (const float*)d_in[8];
    float* out = (float*)d_out;

    unsigned *Xh, *Xl, *Qh, *Ql, *Kh, *Kl, *Vh, *Vl;
    unsigned *Wqh, *Wql, *Wkh, *Wkl, *Wvh, *Wvl, *Woh, *Wol;
    cudaGetSymbolAddress((void**)&Xh, g_Xh);  cudaGetSymbolAddress((void**)&Xl, g_Xl);
    cudaGetSymbolAddress((void**)&Wqh, g_Wqh); cudaGetSymbolAddress((void**)&Wql, g_Wql);
    cudaGetSymbolAddress((void**)&Wkh, g_Wkh); cudaGetSymbolAddress((void**)&Wkl, g_Wkl);
    cudaGetSymbolAddress((void**)&Wvh, g_Wvh); cudaGetSymbolAddress((void**)&Wvl, g_Wvl);
    cudaGetSymbolAddress((void**)&Woh, g_Woh); cudaGetSymbolAddress((void**)&Wol, g_Wol);
    cudaGetSymbolAddress((void**)&Qh, g_Qh);  cudaGetSymbolAddress((void**)&Ql, g_Ql);
    cudaGetSymbolAddress((void**)&Kh, g_Kh);  cudaGetSymbolAddress((void**)&Kl, g_Kl);
    cudaGetSymbolAddress((void**)&Vh, g_Vh);  cudaGetSymbolAddress((void**)&Vl, g_Vl);

    cudaFuncSetAttribute(gemm_qkv_b, cudaFuncAttributeMaxDynamicSharedMemorySize, (int)GEMM_SMEM);
    cudaFuncSetAttribute(gemm_oproj, cudaFuncAttributeMaxDynamicSharedMemorySize, (int)GEMM_SMEM);
    cudaFuncSetAttribute(flash_gqa,  cudaFuncAttributeMaxDynamicSharedMemorySize, (int)FLASH_SMEM);

    // Pack inputs and weights to bf16 hi/lo pairs
    pack_x<<<MROWS * 512 / 256, 256>>>(x, Xh, Xl);
    pack_w<<<dim3(16, QDIM  / 32), 256>>>(Wq, Wqh, Wql, QDIM);
    pack_w<<<dim3(16, KVDIM / 32), 256>>>(Wk, Wkh, Wkl, KVDIM);
    pack_w<<<dim3(16, KVDIM / 32), 256>>>(Wv, Wvh, Wvl, KVDIM);
    pack_w<<<dim3(16, HIDDEN / 32), 256>>>(Wo, Woh, Wol, HIDDEN);

    // Fused QKV projection -> packed Q/K/V
    gemm_qkv_b<<<dim3(12, MROWS / 128), 256, GEMM_SMEM>>>(bq, bk, bv);

    // Flash attention -> packed A
    unsigned *Ahp, *Alp;
    cudaGetSymbolAddress((void**)&Ahp, g_Ah); cudaGetSymbolAddress((void**)&Alp, g_Al);
    flash_gqa<<<dim3(SEQ / 64, BATCH * NH), 128, FLASH_SMEM>>>(Qh, Ql, Kh, Kl, Vh, Vl, Ahp, Alp);

    // Output projection -> d_out (fp32)
    gemm_oproj<<<dim3(HIDDEN / 128, MROWS / 128), 256, GEMM_SMEM>>>(bo, out);
}